// round 11
// baseline (speedup 1.0000x reference)
#include <cuda_runtime.h>
#include <cuda_fp16.h>
#include <cstdint>

// KPConv fully tensorized, pipelined, small-CTA, instruction-minimized.
// inputs: q_pts[N,3], s_pts(unused), neighbors[N,32,3], neighb_inds(unused),
//         x[N,32,64], kernel_points[15,3], weights[15,64,64] -> out[N,64] f32

#define KPTS 15
#define NNB  32
#define CIN  64
#define COUT 64
#define PBLK 16
#define QB   2
#define NQB  8
#define THREADS 256
#define NKS  60                  // 960 / 16
#define ROWB 1920                // wt row stride bytes
#define WT_BYTES (PBLK * ROWB)   // 30720
#define XSH_OFF  WT_BYTES
#define XBUF     8192            // 2 pts * 4096
#define W16_OFF  (XSH_OFF + 2 * XBUF)        // 47104
#define WBUF     2560                        // 2 pts * 1280
#define SMEM_TOTAL (W16_OFF + 2 * WBUF + 1024)

typedef unsigned long long ull;

// B fragments, packed for LDG.128: [ng(4)][ks(60)][lane(32)] -> uint4
//   {nt=2ng:b0,b1, nt=2ng+1:b0,b1}
__device__ uint4 g_Bfrag4[4 * NKS * 32];

static __device__ __forceinline__ uint32_t smem_u32(const void* p) {
    uint32_t a;
    asm("{ .reg .u64 t; cvta.to.shared.u64 t, %1; cvt.u32.u64 %0, t; }" : "=r"(a) : "l"(p));
    return a;
}
static __device__ __forceinline__ void ldm_x4(uint32_t& a0, uint32_t& a1,
                                              uint32_t& a2, uint32_t& a3, uint32_t addr) {
    asm volatile("ldmatrix.sync.aligned.m8n8.x4.shared.b16 {%0,%1,%2,%3}, [%4];"
                 : "=r"(a0), "=r"(a1), "=r"(a2), "=r"(a3) : "r"(addr));
}
static __device__ __forceinline__ void ldm_x4t(uint32_t& a0, uint32_t& a1,
                                               uint32_t& a2, uint32_t& a3, uint32_t addr) {
    asm volatile("ldmatrix.sync.aligned.m8n8.x4.trans.shared.b16 {%0,%1,%2,%3}, [%4];"
                 : "=r"(a0), "=r"(a1), "=r"(a2), "=r"(a3) : "r"(addr));
}
static __device__ __forceinline__ void mma16816(float* c, uint32_t a0, uint32_t a1,
                                                uint32_t a2, uint32_t a3,
                                                uint32_t b0, uint32_t b1) {
    asm volatile("mma.sync.aligned.m16n8k16.row.col.f32.f16.f16.f32 "
                 "{%0,%1,%2,%3}, {%4,%5,%6,%7}, {%8,%9}, {%0,%1,%2,%3};"
                 : "+f"(c[0]), "+f"(c[1]), "+f"(c[2]), "+f"(c[3])
                 : "r"(a0), "r"(a1), "r"(a2), "r"(a3), "r"(b0), "r"(b1));
}
static __device__ __forceinline__ float sqrt_approx(float v) {
    float r;
    asm("sqrt.approx.f32 %0, %1;" : "=f"(r) : "f"(v));
    return r;
}
static __device__ __forceinline__ uint32_t h2u(float lo, float hi) {
    __half2 h = __floats2half2_rn(lo, hi);
    return *(const uint32_t*)&h;
}

__global__ void pack_bfrag(const float* __restrict__ W) {
    int i = blockIdx.x * blockDim.x + threadIdx.x;
    if (i >= 4 * NKS * 32) return;
    int lane = i & 31;
    int ks   = (i >> 5) % NKS;
    int ng   = i / (NKS * 32);
    int n0 = ng * 16 + (lane >> 2);
    int n1 = n0 + 8;
    int j0 = ks * 16 + (lane & 3) * 2;
    uint4 u;
    u.x = h2u(W[(j0 + 0) * COUT + n0], W[(j0 + 1) * COUT + n0]);
    u.y = h2u(W[(j0 + 8) * COUT + n0], W[(j0 + 9) * COUT + n0]);
    u.z = h2u(W[(j0 + 0) * COUT + n1], W[(j0 + 1) * COUT + n1]);
    u.w = h2u(W[(j0 + 8) * COUT + n1], W[(j0 + 9) * COUT + n1]);
    g_Bfrag4[i] = u;
}

__global__ __launch_bounds__(THREADS, 4)
void kpconv_kernel(const float* __restrict__ q_pts,
                   const float* __restrict__ neighbors,
                   const float* __restrict__ x,
                   const float* __restrict__ kernel_points,
                   float* __restrict__ out,
                   int N)
{
    extern __shared__ char smem_raw[];
    char* smem = (char*)(((uintptr_t)smem_raw + 1023) & ~(uintptr_t)1023);
    char* wt_sh = smem;                      // fp16 A tile for phase 3 (16 rows)
    char* x_sh  = smem + XSH_OFF;            // fp16 x tiles, 2 bufs x 2 pts
    char* w16   = smem + W16_OFF;            // fp16 w tiles, 2 bufs x 2 pts
    __shared__ float4 kp4_sh[16];            // {-2kx,-2ky,-2kz, |kp|^2}, pad k=15
    const uint32_t sb_u32  = smem_u32(smem);
    const uint32_t wt_u32  = sb_u32;
    const uint32_t xsh_u32 = sb_u32 + XSH_OFF;
    const uint32_t w16_u32 = sb_u32 + W16_OFF;

    const int tid  = threadIdx.x;
    const int wid  = tid >> 5;
    const int lane = tid & 31;
    const int base = blockIdx.x * PBLK;

    if (tid < 16) {
        float4 v;
        if (tid < KPTS) {
            float kx = kernel_points[tid * 3 + 0];
            float ky = kernel_points[tid * 3 + 1];
            float kz = kernel_points[tid * 3 + 2];
            v = make_float4(-2.f * kx, -2.f * ky, -2.f * kz,
                            kx * kx + ky * ky + kz * kz);
        } else {
            v = make_float4(0.f, 0.f, 0.f, 1e30f);   // pad row -> w = 0
        }
        kp4_sh[tid] = v;
    }
    __syncthreads();

    const float inv_ext = 1.0f / 0.06f;

    // ---- staging geometry (x): warp -> point sp, rows rg*8..rg*8+7 ----
    const int sp = wid >> 2;
    const int rg = wid & 3;
    const int ml = rg * 8 + (lane >> 2);     // m row 0..31
    const int cp = lane & 3;                 // 16-col chunk pair
    const int xg_off = ml * 16 + cp * 4;     // float4 units within point
    const int xs_off = sp * 4096 + ml * 128;
    const int pc0 = (((cp << 1) + 0) ^ (ml & 7)) << 4;
    const int pc1 = (((cp << 1) + 1) ^ (ml & 7)) << 4;

    // ---- phase1 geometry: item (p1, m1), k-quarter kq ----
    const int i1 = tid >> 2;
    const int p1 = i1 >> 5;
    const int m1 = i1 & 31;
    const int kq = tid & 3;
    const int wrow_off = p1 * 1280 + m1 * 2;
    const float4* kq4 = kp4_sh + kq * 4;

    // ---- phase2 geometry ----
    const int p2 = wid >> 2;                 // point 0..1
    const int qn = wid & 3;                  // nt pair
    const int g  = lane >> 3;
    const uint32_t wA0 = w16_u32 + p2 * 1280 + ((g & 1) * 8 + (lane & 7)) * 80
                       + (g >> 1) * 16;      // s=1: +32
    const int row0 = (g & 1) * 8 + (lane & 7);
    const int nt2  = qn * 2 + (g >> 1);
    const uint32_t xB0 = xsh_u32 + p2 * 4096 + row0 * 128
                       + ((nt2 ^ (row0 & 7)) << 4);   // s=1: +2048
    // D-store: X(i,rh) = (kpt0 + 8rh)*8 + qn*2 + i
    const int kpt0 = lane >> 2;
    const int Xa   = kpt0 * 8 + qn * 2;
    const int doff = (lane & 3) * 4;
    const bool rh1ok = kpt0 < 7;

    float4 f0, f1, f2, f3;
    float rx, ry, rz;

#define LDG_X(qb)                                                            \
    {                                                                        \
        int np = base + (qb) * QB + sp; if (np >= N) np = N - 1;             \
        const float4* xr = (const float4*)x + np * 512 + xg_off;             \
        f0 = __ldg(xr + 0); f1 = __ldg(xr + 1);                              \
        f2 = __ldg(xr + 2); f3 = __ldg(xr + 3);                              \
    }

#define LDG_NBR(qb)                                                          \
    {                                                                        \
        int np = base + (qb) * QB + p1; if (np >= N) np = N - 1;             \
        float qx = q_pts[np * 3 + 0];                                        \
        float qy = q_pts[np * 3 + 1];                                        \
        float qz = q_pts[np * 3 + 2];                                        \
        int nb = (np * NNB + m1) * 3;                                        \
        rx = neighbors[nb + 0] - qx;                                         \
        ry = neighbors[nb + 1] - qy;                                         \
        rz = neighbors[nb + 2] - qz;                                         \
    }

#define PHASE1_ST(bw)                                                        \
    {                                                                        \
        float relsq = rx * rx + ry * ry + rz * rz;                           \
        char* wrow = w16 + (bw) + wrow_off;                                  \
        _Pragma("unroll")                                                    \
        for (int kk = 0; kk < 4; kk++) {                                     \
            float4 kv = kq4[kk];                                             \
            float sq = relsq + kv.w;                                         \
            sq = fmaf(kv.x, rx, sq);                                         \
            sq = fmaf(kv.y, ry, sq);                                         \
            sq = fmaf(kv.z, rz, sq);                                         \
            sq = fmaxf(sq, 0.0f);                                            \
            float w = fmaxf(fmaf(sqrt_approx(sq), -inv_ext, 1.0f), 0.0f);    \
            *(__half*)(wrow + (kq * 4 + kk) * 80) = __float2half_rn(w);      \
        }                                                                    \
    }

#define STS_X(bx)                                                            \
    {                                                                        \
        char* xt = x_sh + (bx) + xs_off;                                     \
        uint4 u;                                                             \
        u.x = h2u(f0.x, f0.y); u.y = h2u(f0.z, f0.w);                        \
        u.z = h2u(f1.x, f1.y); u.w = h2u(f1.z, f1.w);                        \
        *(uint4*)(xt + pc0) = u;                                             \
        u.x = h2u(f2.x, f2.y); u.y = h2u(f2.z, f2.w);                        \
        u.z = h2u(f3.x, f3.y); u.w = h2u(f3.z, f3.w);                        \
        *(uint4*)(xt + pc1) = u;                                             \
    }

    // ---------- prologue ----------
    LDG_X(0)
    LDG_NBR(0)
    PHASE1_ST(0)
    STS_X(0)
    __syncthreads();

    // ---------- pipelined main loop ----------
    #pragma unroll 1
    for (int q = 0; q < NQB; q++) {
        if (q < NQB - 1) {
            LDG_X(q + 1)
            LDG_NBR(q + 1)
        }

        // ---- phase2 MMA for qb=q: wt[16][64] = w[16][32] @ x[32][64] ----
        {
            const int bw = (q & 1) * WBUF;
            const int bx = (q & 1) * XBUF;

            float d0[4] = {0.f, 0.f, 0.f, 0.f};
            float d1[4] = {0.f, 0.f, 0.f, 0.f};
            {
                uint32_t a0, a1, a2, a3, b0, b1, b2, b3;
                ldm_x4 (a0, a1, a2, a3, wA0 + bw);
                ldm_x4t(b0, b1, b2, b3, xB0 + bx);
                mma16816(d0, a0, a1, a2, a3, b0, b1);
                mma16816(d1, a0, a1, a2, a3, b2, b3);
                ldm_x4 (a0, a1, a2, a3, wA0 + bw + 32);
                ldm_x4t(b0, b1, b2, b3, xB0 + bx + 2048);
                mma16816(d0, a0, a1, a2, a3, b0, b1);
                mma16816(d1, a0, a1, a2, a3, b2, b3);
            }

            // store D -> WT tile (phase-3 A layout)
            const int lr = q * QB + p2;
            const int sw = lr & 7;
            char* dbase = wt_sh + lr * ROWB + doff;
            *(__half2*)(dbase + (((Xa + 0) ^ sw) << 4))
                = __floats2half2_rn(d0[0], d0[1]);
            *(__half2*)(dbase + (((Xa + 1) ^ sw) << 4))
                = __floats2half2_rn(d1[0], d1[1]);
            if (rh1ok) {
                *(__half2*)(dbase + (((Xa + 64) ^ sw) << 4))
                    = __floats2half2_rn(d0[2], d0[3]);
                *(__half2*)(dbase + (((Xa + 65) ^ sw) << 4))
                    = __floats2half2_rn(d1[2], d1[3]);
            }
        }

        if (q < NQB - 1) {
            PHASE1_ST(((q + 1) & 1) * WBUF)
            STS_X(((q + 1) & 1) * XBUF)
        }
        __syncthreads();
    }

    // ---------- Phase 3: HMMA GEMM out[16][64] = wt @ W ----------
    {
        const int kh = wid >> 2;                 // K-half
        const int ng = wid & 3;                  // n-group (2 n-tiles)
        const int rowA = lane & 15;
        const uint32_t a_row = wt_u32 + rowA * ROWB;
        const int swA = rowA & 7;
        const int ks2b = kh * NKS + (lane >> 4); // 2*ks + khalf base

        float c0[4] = {0.f, 0.f, 0.f, 0.f};
        float c1[4] = {0.f, 0.f, 0.f, 0.f};
        const uint4* Bf = g_Bfrag4 + (ng * NKS + kh * (NKS / 2)) * 32 + lane;

        #pragma unroll 5
        for (int s = 0; s < NKS / 2; s++) {
            uint32_t addr = a_row + (((ks2b + 2 * s) ^ swA) << 4);
            uint32_t a0, a1, a2, a3;
            ldm_x4(a0, a1, a2, a3, addr);
            uint4 b = __ldg(Bf + s * 32);
            mma16816(c0, a0, a1, a2, a3, b.x, b.y);
            mma16816(c1, a0, a1, a2, a3, b.z, b.w);
        }

        // reduce across K-halves via smem (alias over x_sh), float4 ops
        float4* red4 = (float4*)x_sh;            // 4KB <= 16KB
        __syncthreads();
        if (kh == 1) {
            red4[(ng * 2 + 0) * 32 + lane] = make_float4(c0[0], c0[1], c0[2], c0[3]);
            red4[(ng * 2 + 1) * 32 + lane] = make_float4(c1[0], c1[1], c1[2], c1[3]);
        }
        __syncthreads();
        if (kh == 0) {
            float4 r0 = red4[(ng * 2 + 0) * 32 + lane];
            float4 r1 = red4[(ng * 2 + 1) * 32 + lane];
            c0[0] += r0.x; c0[1] += r0.y; c0[2] += r0.z; c0[3] += r0.w;
            c1[0] += r1.x; c1[1] += r1.y; c1[2] += r1.z; c1[3] += r1.w;
            int ro0 = base + (lane >> 2);
            int ro1 = ro0 + 8;
            int col0 = (ng * 2 + 0) * 8 + (lane & 3) * 2;
            int col1 = (ng * 2 + 1) * 8 + (lane & 3) * 2;
            if (ro0 < N) {
                *(float2*)&out[(long long)ro0 * COUT + col0] = make_float2(c0[0], c0[1]);
                *(float2*)&out[(long long)ro0 * COUT + col1] = make_float2(c1[0], c1[1]);
            }
            if (ro1 < N) {
                *(float2*)&out[(long long)ro1 * COUT + col0] = make_float2(c0[2], c0[3]);
                *(float2*)&out[(long long)ro1 * COUT + col1] = make_float2(c1[2], c1[3]);
            }
        }
    }
}

extern "C" void kernel_launch(void* const* d_in, const int* in_sizes, int n_in,
                              void* d_out, int out_size) {
    const float* q_pts     = (const float*)d_in[0];
    const float* neighbors = (const float*)d_in[2];
    const float* x         = (const float*)d_in[4];
    const float* kp        = (const float*)d_in[5];
    const float* W         = (const float*)d_in[6];
    float* out = (float*)d_out;

    int N = in_sizes[0] / 3;

    cudaFuncSetAttribute(kpconv_kernel,
                         cudaFuncAttributeMaxDynamicSharedMemorySize, SMEM_TOTAL);

    pack_bfrag<<<(4 * NKS * 32 + 255) / 256, 256>>>(W);
    int grid = (N + PBLK - 1) / PBLK;
    kpconv_kernel<<<grid, THREADS, SMEM_TOTAL>>>(q_pts, neighbors, x, kp, out, N);
}

// round 12
// speedup vs baseline: 1.1737x; 1.1737x over previous
#include <cuda_runtime.h>
#include <cuda_fp16.h>
#include <cstdint>

// KPConv fully tensorized, pipelined, small-CTA, instruction-minimized,
// with COALESCED x loads (R9 mapping) restored.
// inputs: q_pts[N,3], s_pts(unused), neighbors[N,32,3], neighb_inds(unused),
//         x[N,32,64], kernel_points[15,3], weights[15,64,64] -> out[N,64] f32

#define KPTS 15
#define NNB  32
#define CIN  64
#define COUT 64
#define PBLK 16
#define QB   2
#define NQB  8
#define THREADS 256
#define NKS  60                  // 960 / 16
#define ROWB 1920                // wt row stride bytes
#define WT_BYTES (PBLK * ROWB)   // 30720
#define XSH_OFF  WT_BYTES
#define XBUF     8192            // 2 pts * 4096
#define W16_OFF  (XSH_OFF + 2 * XBUF)        // 47104
#define WBUF     2560                        // 2 pts * 1280
#define SMEM_TOTAL (W16_OFF + 2 * WBUF + 1024)

typedef unsigned long long ull;

// B fragments, packed for LDG.128: [ng(4)][ks(60)][lane(32)] -> uint4
__device__ uint4 g_Bfrag4[4 * NKS * 32];

static __device__ __forceinline__ uint32_t smem_u32(const void* p) {
    uint32_t a;
    asm("{ .reg .u64 t; cvta.to.shared.u64 t, %1; cvt.u32.u64 %0, t; }" : "=r"(a) : "l"(p));
    return a;
}
static __device__ __forceinline__ void ldm_x4(uint32_t& a0, uint32_t& a1,
                                              uint32_t& a2, uint32_t& a3, uint32_t addr) {
    asm volatile("ldmatrix.sync.aligned.m8n8.x4.shared.b16 {%0,%1,%2,%3}, [%4];"
                 : "=r"(a0), "=r"(a1), "=r"(a2), "=r"(a3) : "r"(addr));
}
static __device__ __forceinline__ void ldm_x4t(uint32_t& a0, uint32_t& a1,
                                               uint32_t& a2, uint32_t& a3, uint32_t addr) {
    asm volatile("ldmatrix.sync.aligned.m8n8.x4.trans.shared.b16 {%0,%1,%2,%3}, [%4];"
                 : "=r"(a0), "=r"(a1), "=r"(a2), "=r"(a3) : "r"(addr));
}
static __device__ __forceinline__ void mma16816(float* c, uint32_t a0, uint32_t a1,
                                                uint32_t a2, uint32_t a3,
                                                uint32_t b0, uint32_t b1) {
    asm volatile("mma.sync.aligned.m16n8k16.row.col.f32.f16.f16.f32 "
                 "{%0,%1,%2,%3}, {%4,%5,%6,%7}, {%8,%9}, {%0,%1,%2,%3};"
                 : "+f"(c[0]), "+f"(c[1]), "+f"(c[2]), "+f"(c[3])
                 : "r"(a0), "r"(a1), "r"(a2), "r"(a3), "r"(b0), "r"(b1));
}
static __device__ __forceinline__ float sqrt_approx(float v) {
    float r;
    asm("sqrt.approx.f32 %0, %1;" : "=f"(r) : "f"(v));
    return r;
}
static __device__ __forceinline__ uint32_t h2u(float lo, float hi) {
    __half2 h = __floats2half2_rn(lo, hi);
    return *(const uint32_t*)&h;
}

__global__ void pack_bfrag(const float* __restrict__ W) {
    int i = blockIdx.x * blockDim.x + threadIdx.x;
    if (i >= 4 * NKS * 32) return;
    int lane = i & 31;
    int ks   = (i >> 5) % NKS;
    int ng   = i / (NKS * 32);
    int n0 = ng * 16 + (lane >> 2);
    int n1 = n0 + 8;
    int j0 = ks * 16 + (lane & 3) * 2;
    uint4 u;
    u.x = h2u(W[(j0 + 0) * COUT + n0], W[(j0 + 1) * COUT + n0]);
    u.y = h2u(W[(j0 + 8) * COUT + n0], W[(j0 + 9) * COUT + n0]);
    u.z = h2u(W[(j0 + 0) * COUT + n1], W[(j0 + 1) * COUT + n1]);
    u.w = h2u(W[(j0 + 8) * COUT + n1], W[(j0 + 9) * COUT + n1]);
    g_Bfrag4[i] = u;
}

__global__ __launch_bounds__(THREADS, 4)
void kpconv_kernel(const float* __restrict__ q_pts,
                   const float* __restrict__ neighbors,
                   const float* __restrict__ x,
                   const float* __restrict__ kernel_points,
                   float* __restrict__ out,
                   int N)
{
    extern __shared__ char smem_raw[];
    char* smem = (char*)(((uintptr_t)smem_raw + 1023) & ~(uintptr_t)1023);
    char* wt_sh = smem;                      // fp16 A tile for phase 3 (16 rows)
    char* x_sh  = smem + XSH_OFF;            // fp16 x tiles, 2 bufs x 2 pts
    char* w16   = smem + W16_OFF;            // fp16 w tiles, 2 bufs x 2 pts
    __shared__ float4 kp4_sh[16];            // {-2kx,-2ky,-2kz, |kp|^2}, pad k=15
    const uint32_t sb_u32  = smem_u32(smem);
    const uint32_t wt_u32  = sb_u32;
    const uint32_t xsh_u32 = sb_u32 + XSH_OFF;
    const uint32_t w16_u32 = sb_u32 + W16_OFF;

    const int tid  = threadIdx.x;
    const int wid  = tid >> 5;
    const int lane = tid & 31;
    const int base = blockIdx.x * PBLK;

    if (tid < 16) {
        float4 v;
        if (tid < KPTS) {
            float kx = kernel_points[tid * 3 + 0];
            float ky = kernel_points[tid * 3 + 1];
            float kz = kernel_points[tid * 3 + 2];
            v = make_float4(-2.f * kx, -2.f * ky, -2.f * kz,
                            kx * kx + ky * ky + kz * kz);
        } else {
            v = make_float4(0.f, 0.f, 0.f, 1e30f);   // pad row -> w = 0
        }
        kp4_sh[tid] = v;
    }
    __syncthreads();

    const float inv_ext = 1.0f / 0.06f;

    // ---- staging geometry (x): warp -> point sp, rows rg*8..rg*8+7 (coalesced) ----
    const int sp = wid >> 2;
    const int rg = wid & 3;
    const int m0 = rg * 8 + (lane >> 4);     // rows m0, m0+2, m0+4, m0+6
    const int c4 = (lane & 15) * 4;          // float column base
    const int xg_off = m0 * 16 + (lane & 15);        // float4 units within point
    const int xs_base = sp * 4096;

    // ---- phase1 geometry: item (p1, m1), k-quarter kq ----
    const int i1 = tid >> 2;
    const int p1 = i1 >> 5;
    const int m1 = i1 & 31;
    const int kq = tid & 3;
    const int wrow_off = p1 * 1280 + m1 * 2;
    const float4* kq4 = kp4_sh + kq * 4;

    // ---- phase2 geometry ----
    const int p2 = wid >> 2;                 // point 0..1
    const int qn = wid & 3;                  // nt pair
    const int g  = lane >> 3;
    const uint32_t wA0 = w16_u32 + p2 * 1280 + ((g & 1) * 8 + (lane & 7)) * 80
                       + (g >> 1) * 16;      // s=1: +32
    const int row0 = (g & 1) * 8 + (lane & 7);
    const int nt2  = qn * 2 + (g >> 1);
    const uint32_t xB0 = xsh_u32 + p2 * 4096 + row0 * 128
                       + ((nt2 ^ (row0 & 7)) << 4);   // s=1: +2048
    // D-store: X(i,rh) = (kpt0 + 8rh)*8 + qn*2 + i
    const int kpt0 = lane >> 2;
    const int Xa   = kpt0 * 8 + qn * 2;
    const int doff = (lane & 3) * 4;
    const bool rh1ok = kpt0 < 7;

    float4 f0, f1, f2, f3;
    float rx, ry, rz;

#define LDG_X(qb)                                                            \
    {                                                                        \
        int np = base + (qb) * QB + sp; if (np >= N) np = N - 1;             \
        const float4* xr = (const float4*)x + np * 512 + xg_off;             \
        f0 = __ldg(xr + 0 * 32); f1 = __ldg(xr + 1 * 32);                    \
        f2 = __ldg(xr + 2 * 32); f3 = __ldg(xr + 3 * 32);                    \
    }

#define LDG_NBR(qb)                                                          \
    {                                                                        \
        int np = base + (qb) * QB + p1; if (np >= N) np = N - 1;             \
        float qx = q_pts[np * 3 + 0];                                        \
        float qy = q_pts[np * 3 + 1];                                        \
        float qz = q_pts[np * 3 + 2];                                        \
        int nb = (np * NNB + m1) * 3;                                        \
        rx = neighbors[nb + 0] - qx;                                         \
        ry = neighbors[nb + 1] - qy;                                         \
        rz = neighbors[nb + 2] - qz;                                         \
    }

#define PHASE1_ST(bw)                                                        \
    {                                                                        \
        float relsq = rx * rx + ry * ry + rz * rz;                           \
        char* wrow = w16 + (bw) + wrow_off;                                  \
        _Pragma("unroll")                                                    \
        for (int kk = 0; kk < 4; kk++) {                                     \
            float4 kv = kq4[kk];                                             \
            float sq = relsq + kv.w;                                         \
            sq = fmaf(kv.x, rx, sq);                                         \
            sq = fmaf(kv.y, ry, sq);                                         \
            sq = fmaf(kv.z, rz, sq);                                         \
            sq = fmaxf(sq, 0.0f);                                            \
            float w = fmaxf(fmaf(sqrt_approx(sq), -inv_ext, 1.0f), 0.0f);    \
            *(__half*)(wrow + (kq * 4 + kk) * 80) = __float2half_rn(w);      \
        }                                                                    \
    }

// coalesced-layout STS: per it, thread holds 16B fp32 of row (m0+2it) -> 8B fp16
#define STS_X1(xt, it, fa)                                                   \
    {                                                                        \
        int m = m0 + 2 * (it);                                               \
        uint2 st;                                                            \
        st.x = h2u((fa).x, (fa).y);                                          \
        st.y = h2u((fa).z, (fa).w);                                          \
        int chunk = (c4 >> 3) ^ (m & 7);                                     \
        *(uint2*)((xt) + m * 128 + chunk * 16 + (c4 & 7) * 2) = st;          \
    }

#define STS_X(bx)                                                            \
    {                                                                        \
        char* xt = x_sh + (bx) + xs_base;                                    \
        STS_X1(xt, 0, f0)                                                    \
        STS_X1(xt, 1, f1)                                                    \
        STS_X1(xt, 2, f2)                                                    \
        STS_X1(xt, 3, f3)                                                    \
    }

    // ---------- prologue ----------
    LDG_X(0)
    LDG_NBR(0)
    PHASE1_ST(0)
    STS_X(0)
    __syncthreads();

    // ---------- pipelined main loop ----------
    #pragma unroll 1
    for (int q = 0; q < NQB; q++) {
        if (q < NQB - 1) {
            LDG_X(q + 1)
            LDG_NBR(q + 1)
        }

        // ---- phase2 MMA for qb=q: wt[16][64] = w[16][32] @ x[32][64] ----
        {
            const int bw = (q & 1) * WBUF;
            const int bx = (q & 1) * XBUF;

            float d0[4] = {0.f, 0.f, 0.f, 0.f};
            float d1[4] = {0.f, 0.f, 0.f, 0.f};
            {
                uint32_t a0, a1, a2, a3, b0, b1, b2, b3;
                ldm_x4 (a0, a1, a2, a3, wA0 + bw);
                ldm_x4t(b0, b1, b2, b3, xB0 + bx);
                mma16816(d0, a0, a1, a2, a3, b0, b1);
                mma16816(d1, a0, a1, a2, a3, b2, b3);
                ldm_x4 (a0, a1, a2, a3, wA0 + bw + 32);
                ldm_x4t(b0, b1, b2, b3, xB0 + bx + 2048);
                mma16816(d0, a0, a1, a2, a3, b0, b1);
                mma16816(d1, a0, a1, a2, a3, b2, b3);
            }

            // store D -> WT tile (phase-3 A layout)
            const int lr = q * QB + p2;
            const int sw = lr & 7;
            char* dbase = wt_sh + lr * ROWB + doff;
            *(__half2*)(dbase + (((Xa + 0) ^ sw) << 4))
                = __floats2half2_rn(d0[0], d0[1]);
            *(__half2*)(dbase + (((Xa + 1) ^ sw) << 4))
                = __floats2half2_rn(d1[0], d1[1]);
            if (rh1ok) {
                *(__half2*)(dbase + (((Xa + 64) ^ sw) << 4))
                    = __floats2half2_rn(d0[2], d0[3]);
                *(__half2*)(dbase + (((Xa + 65) ^ sw) << 4))
                    = __floats2half2_rn(d1[2], d1[3]);
            }
        }

        if (q < NQB - 1) {
            PHASE1_ST(((q + 1) & 1) * WBUF)
            STS_X(((q + 1) & 1) * XBUF)
        }
        __syncthreads();
    }

    // ---------- Phase 3: HMMA GEMM out[16][64] = wt @ W ----------
    {
        const int kh = wid >> 2;                 // K-half
        const int ng = wid & 3;                  // n-group (2 n-tiles)
        const int rowA = lane & 15;
        const uint32_t a_row = wt_u32 + rowA * ROWB;
        const int swA = rowA & 7;
        const int ks2b = kh * NKS + (lane >> 4); // 2*ks + khalf base

        float c0[4] = {0.f, 0.f, 0.f, 0.f};
        float c1[4] = {0.f, 0.f, 0.f, 0.f};
        const uint4* Bf = g_Bfrag4 + (ng * NKS + kh * (NKS / 2)) * 32 + lane;

        #pragma unroll 5
        for (int s = 0; s < NKS / 2; s++) {
            uint32_t addr = a_row + (((ks2b + 2 * s) ^ swA) << 4);
            uint32_t a0, a1, a2, a3;
            ldm_x4(a0, a1, a2, a3, addr);
            uint4 b = __ldg(Bf + s * 32);
            mma16816(c0, a0, a1, a2, a3, b.x, b.y);
            mma16816(c1, a0, a1, a2, a3, b.z, b.w);
        }

        // reduce across K-halves via smem (alias over x_sh), float4 ops
        float4* red4 = (float4*)x_sh;            // 4KB <= 16KB
        __syncthreads();
        if (kh == 1) {
            red4[(ng * 2 + 0) * 32 + lane] = make_float4(c0[0], c0[1], c0[2], c0[3]);
            red4[(ng * 2 + 1) * 32 + lane] = make_float4(c1[0], c1[1], c1[2], c1[3]);
        }
        __syncthreads();
        if (kh == 0) {
            float4 r0 = red4[(ng * 2 + 0) * 32 + lane];
            float4 r1 = red4[(ng * 2 + 1) * 32 + lane];
            c0[0] += r0.x; c0[1] += r0.y; c0[2] += r0.z; c0[3] += r0.w;
            c1[0] += r1.x; c1[1] += r1.y; c1[2] += r1.z; c1[3] += r1.w;
            int ro0 = base + (lane >> 2);
            int ro1 = ro0 + 8;
            int col0 = (ng * 2 + 0) * 8 + (lane & 3) * 2;
            int col1 = (ng * 2 + 1) * 8 + (lane & 3) * 2;
            if (ro0 < N) {
                *(float2*)&out[(long long)ro0 * COUT + col0] = make_float2(c0[0], c0[1]);
                *(float2*)&out[(long long)ro0 * COUT + col1] = make_float2(c1[0], c1[1]);
            }
            if (ro1 < N) {
                *(float2*)&out[(long long)ro1 * COUT + col0] = make_float2(c0[2], c0[3]);
                *(float2*)&out[(long long)ro1 * COUT + col1] = make_float2(c1[2], c1[3]);
            }
        }
    }
}

extern "C" void kernel_launch(void* const* d_in, const int* in_sizes, int n_in,
                              void* d_out, int out_size) {
    const float* q_pts     = (const float*)d_in[0];
    const float* neighbors = (const float*)d_in[2];
    const float* x         = (const float*)d_in[4];
    const float* kp        = (const float*)d_in[5];
    const float* W         = (const float*)d_in[6];
    float* out = (float*)d_out;

    int N = in_sizes[0] / 3;

    cudaFuncSetAttribute(kpconv_kernel,
                         cudaFuncAttributeMaxDynamicSharedMemorySize, SMEM_TOTAL);

    pack_bfrag<<<(4 * NKS * 32 + 255) / 256, 256>>>(W);
    int grid = (N + PBLK - 1) / PBLK;
    kpconv_kernel<<<grid, THREADS, SMEM_TOTAL>>>(q_pts, neighbors, x, kp, out, N);
}

// round 13
// speedup vs baseline: 1.1942x; 1.0174x over previous
#include <cuda_runtime.h>
#include <cuda_fp16.h>
#include <cstdint>

// KPConv fully tensorized, pipelined, small-CTA, instruction-minimized,
// coalesced x loads, u32 shared-store addressing (register-pressure relief).
// inputs: q_pts[N,3], s_pts(unused), neighbors[N,32,3], neighb_inds(unused),
//         x[N,32,64], kernel_points[15,3], weights[15,64,64] -> out[N,64] f32

#define KPTS 15
#define NNB  32
#define CIN  64
#define COUT 64
#define PBLK 16
#define QB   2
#define NQB  8
#define THREADS 256
#define NKS  60                  // 960 / 16
#define ROWB 1920                // wt row stride bytes
#define WT_BYTES (PBLK * ROWB)   // 30720
#define XSH_OFF  WT_BYTES
#define XBUF     8192            // 2 pts * 4096
#define W16_OFF  (XSH_OFF + 2 * XBUF)        // 47104
#define WBUF     2560                        // 2 pts * 1280
#define SMEM_TOTAL (W16_OFF + 2 * WBUF + 1024)

typedef unsigned long long ull;

// B fragments, packed for LDG.128: [ng(4)][ks(60)][lane(32)] -> uint4
__device__ uint4 g_Bfrag4[4 * NKS * 32];

static __device__ __forceinline__ uint32_t smem_u32(const void* p) {
    uint32_t a;
    asm("{ .reg .u64 t; cvta.to.shared.u64 t, %1; cvt.u32.u64 %0, t; }" : "=r"(a) : "l"(p));
    return a;
}
static __device__ __forceinline__ void sts16(uint32_t addr, uint16_t v) {
    asm volatile("st.shared.u16 [%0], %1;" :: "r"(addr), "h"(v));
}
static __device__ __forceinline__ void sts32(uint32_t addr, uint32_t v) {
    asm volatile("st.shared.b32 [%0], %1;" :: "r"(addr), "r"(v));
}
static __device__ __forceinline__ void sts64(uint32_t addr, uint32_t a, uint32_t b) {
    asm volatile("st.shared.v2.b32 [%0], {%1,%2};" :: "r"(addr), "r"(a), "r"(b));
}
static __device__ __forceinline__ void ldm_x4(uint32_t& a0, uint32_t& a1,
                                              uint32_t& a2, uint32_t& a3, uint32_t addr) {
    asm volatile("ldmatrix.sync.aligned.m8n8.x4.shared.b16 {%0,%1,%2,%3}, [%4];"
                 : "=r"(a0), "=r"(a1), "=r"(a2), "=r"(a3) : "r"(addr));
}
static __device__ __forceinline__ void ldm_x4t(uint32_t& a0, uint32_t& a1,
                                               uint32_t& a2, uint32_t& a3, uint32_t addr) {
    asm volatile("ldmatrix.sync.aligned.m8n8.x4.trans.shared.b16 {%0,%1,%2,%3}, [%4];"
                 : "=r"(a0), "=r"(a1), "=r"(a2), "=r"(a3) : "r"(addr));
}
static __device__ __forceinline__ void mma16816(float* c, uint32_t a0, uint32_t a1,
                                                uint32_t a2, uint32_t a3,
                                                uint32_t b0, uint32_t b1) {
    asm volatile("mma.sync.aligned.m16n8k16.row.col.f32.f16.f16.f32 "
                 "{%0,%1,%2,%3}, {%4,%5,%6,%7}, {%8,%9}, {%0,%1,%2,%3};"
                 : "+f"(c[0]), "+f"(c[1]), "+f"(c[2]), "+f"(c[3])
                 : "r"(a0), "r"(a1), "r"(a2), "r"(a3), "r"(b0), "r"(b1));
}
static __device__ __forceinline__ float sqrt_approx(float v) {
    float r;
    asm("sqrt.approx.f32 %0, %1;" : "=f"(r) : "f"(v));
    return r;
}
static __device__ __forceinline__ uint32_t h2u(float lo, float hi) {
    __half2 h = __floats2half2_rn(lo, hi);
    return *(const uint32_t*)&h;
}
static __device__ __forceinline__ uint16_t h1u(float v) {
    __half h = __float2half_rn(v);
    return *(const uint16_t*)&h;
}

__global__ void pack_bfrag(const float* __restrict__ W) {
    int i = blockIdx.x * blockDim.x + threadIdx.x;
    if (i >= 4 * NKS * 32) return;
    int lane = i & 31;
    int ks   = (i >> 5) % NKS;
    int ng   = i / (NKS * 32);
    int n0 = ng * 16 + (lane >> 2);
    int n1 = n0 + 8;
    int j0 = ks * 16 + (lane & 3) * 2;
    uint4 u;
    u.x = h2u(W[(j0 + 0) * COUT + n0], W[(j0 + 1) * COUT + n0]);
    u.y = h2u(W[(j0 + 8) * COUT + n0], W[(j0 + 9) * COUT + n0]);
    u.z = h2u(W[(j0 + 0) * COUT + n1], W[(j0 + 1) * COUT + n1]);
    u.w = h2u(W[(j0 + 8) * COUT + n1], W[(j0 + 9) * COUT + n1]);
    g_Bfrag4[i] = u;
}

__global__ __launch_bounds__(THREADS, 4)
void kpconv_kernel(const float* __restrict__ q_pts,
                   const float* __restrict__ neighbors,
                   const float* __restrict__ x,
                   const float* __restrict__ kernel_points,
                   float* __restrict__ out,
                   int N)
{
    extern __shared__ char smem_raw[];
    char* smem = (char*)(((uintptr_t)smem_raw + 1023) & ~(uintptr_t)1023);
    __shared__ float4 kp4_sh[16];            // {-2kx,-2ky,-2kz, |kp|^2}, pad k=15
    const uint32_t sb_u32  = smem_u32(smem);
    const uint32_t wt_u32  = sb_u32;                 // fp16 A tile, 16 rows
    const uint32_t xsh_u32 = sb_u32 + XSH_OFF;       // fp16 x tiles, 2 bufs
    const uint32_t w16_u32 = sb_u32 + W16_OFF;       // fp16 w tiles, 2 bufs

    const int tid  = threadIdx.x;
    const int wid  = tid >> 5;
    const int lane = tid & 31;
    const int base = blockIdx.x * PBLK;

    if (tid < 16) {
        float4 v;
        if (tid < KPTS) {
            float kx = kernel_points[tid * 3 + 0];
            float ky = kernel_points[tid * 3 + 1];
            float kz = kernel_points[tid * 3 + 2];
            v = make_float4(-2.f * kx, -2.f * ky, -2.f * kz,
                            kx * kx + ky * ky + kz * kz);
        } else {
            v = make_float4(0.f, 0.f, 0.f, 1e30f);   // pad row -> w = 0
        }
        kp4_sh[tid] = v;
    }
    __syncthreads();

    const float inv_ext = 1.0f / 0.06f;

    // ---- staging geometry (x): warp -> point sp, rows rg*8.. (coalesced) ----
    const int sp = wid >> 2;
    const int rg = wid & 3;
    const int m0 = rg * 8 + (lane >> 4);     // rows m0, m0+2, m0+4, m0+6
    const int c4 = (lane & 15) * 4;          // float column base
    const int xg_off = m0 * 16 + (lane & 15);        // float4 units within point
    // within-row smem byte offset (swizzle varies only with m&7, same for all 4 rows? no:
    // m&7 changes with it; keep per-store compute)
    const uint32_t xs_base = xsh_u32 + sp * 4096;

    // ---- phase1 geometry: item (p1, m1), k-quarter kq ----
    const int p1 = (tid >> 2) >> 5;
    const int m1 = (tid >> 2) & 31;
    const int kq = tid & 3;
    const uint32_t wrow_base = w16_u32 + p1 * 1280 + m1 * 2 + kq * 4 * 80;

    float4 f0, f1, f2, f3;
    float rx, ry, rz;

#define LDG_X(qb)                                                            \
    {                                                                        \
        int np = base + (qb) * QB + sp; if (np >= N) np = N - 1;             \
        const float4* xr = (const float4*)x + np * 512 + xg_off;             \
        f0 = __ldg(xr + 0 * 32); f1 = __ldg(xr + 1 * 32);                    \
        f2 = __ldg(xr + 2 * 32); f3 = __ldg(xr + 3 * 32);                    \
    }

#define LDG_NBR(qb)                                                          \
    {                                                                        \
        int np = base + (qb) * QB + p1; if (np >= N) np = N - 1;             \
        float qx = q_pts[np * 3 + 0];                                        \
        float qy = q_pts[np * 3 + 1];                                        \
        float qz = q_pts[np * 3 + 2];                                        \
        int nb = (np * NNB + m1) * 3;                                        \
        rx = neighbors[nb + 0] - qx;                                         \
        ry = neighbors[nb + 1] - qy;                                         \
        rz = neighbors[nb + 2] - qz;                                         \
    }

#define PHASE1_ST(bw)                                                        \
    {                                                                        \
        float relsq = rx * rx + ry * ry + rz * rz;                           \
        uint32_t wrow = wrow_base + (bw);                                    \
        _Pragma("unroll")                                                    \
        for (int kk = 0; kk < 4; kk++) {                                     \
            float4 kv = kp4_sh[kq * 4 + kk];                                 \
            float sq = relsq + kv.w;                                         \
            sq = fmaf(kv.x, rx, sq);                                         \
            sq = fmaf(kv.y, ry, sq);                                         \
            sq = fmaf(kv.z, rz, sq);                                         \
            sq = fmaxf(sq, 0.0f);                                            \
            float w = fmaxf(fmaf(sqrt_approx(sq), -inv_ext, 1.0f), 0.0f);    \
            sts16(wrow + kk * 80, h1u(w));                                   \
        }                                                                    \
    }

// coalesced-layout STS: per it, thread holds 16B fp32 of row (m0+2it) -> 8B fp16
#define STS_X1(xb, it, fa)                                                   \
    {                                                                        \
        int m = m0 + 2 * (it);                                               \
        int chunk = (c4 >> 3) ^ (m & 7);                                     \
        sts64((xb) + m * 128 + chunk * 16 + (c4 & 7) * 2,                    \
              h2u((fa).x, (fa).y), h2u((fa).z, (fa).w));                     \
    }

#define STS_X(bx)                                                            \
    {                                                                        \
        uint32_t xb = xs_base + (bx);                                        \
        STS_X1(xb, 0, f0)                                                    \
        STS_X1(xb, 1, f1)                                                    \
        STS_X1(xb, 2, f2)                                                    \
        STS_X1(xb, 3, f3)                                                    \
    }

    // ---------- prologue ----------
    LDG_X(0)
    LDG_NBR(0)
    PHASE1_ST(0)
    STS_X(0)
    __syncthreads();

    // ---------- pipelined main loop ----------
    #pragma unroll 1
    for (int q = 0; q < NQB; q++) {
        if (q < NQB - 1) {
            LDG_X(q + 1)
            LDG_NBR(q + 1)
        }

        // ---- phase2 MMA for qb=q: wt[16][64] = w[16][32] @ x[32][64] ----
        {
            const int bw = (q & 1) * WBUF;
            const int bx = (q & 1) * XBUF;
            const int p2 = wid >> 2;
            const int qn = wid & 3;
            const int g  = lane >> 3;
            const uint32_t wA = w16_u32 + bw + p2 * 1280
                              + ((g & 1) * 8 + (lane & 7)) * 80 + (g >> 1) * 16;
            const int row0 = (g & 1) * 8 + (lane & 7);
            const int nt2  = qn * 2 + (g >> 1);
            const uint32_t xB = xsh_u32 + bx + p2 * 4096 + row0 * 128
                              + ((nt2 ^ (row0 & 7)) << 4);

            float d0[4] = {0.f, 0.f, 0.f, 0.f};
            float d1[4] = {0.f, 0.f, 0.f, 0.f};
            {
                uint32_t a0, a1, a2, a3, b0, b1, b2, b3;
                ldm_x4 (a0, a1, a2, a3, wA);
                ldm_x4t(b0, b1, b2, b3, xB);
                mma16816(d0, a0, a1, a2, a3, b0, b1);
                mma16816(d1, a0, a1, a2, a3, b2, b3);
                ldm_x4 (a0, a1, a2, a3, wA + 32);
                ldm_x4t(b0, b1, b2, b3, xB + 2048);
                mma16816(d0, a0, a1, a2, a3, b0, b1);
                mma16816(d1, a0, a1, a2, a3, b2, b3);
            }

            // store D -> WT tile (phase-3 A layout)
            const int lr = q * QB + p2;
            const int sw = lr & 7;
            const int kpt0 = lane >> 2;
            const int Xa   = kpt0 * 8 + qn * 2;
            const uint32_t dbase = wt_u32 + lr * ROWB + (lane & 3) * 4;
            sts32(dbase + (((Xa + 0) ^ sw) << 4), h2u(d0[0], d0[1]));
            sts32(dbase + (((Xa + 1) ^ sw) << 4), h2u(d1[0], d1[1]));
            if (kpt0 < 7) {
                sts32(dbase + (((Xa + 64) ^ sw) << 4), h2u(d0[2], d0[3]));
                sts32(dbase + (((Xa + 65) ^ sw) << 4), h2u(d1[2], d1[3]));
            }
        }

        if (q < NQB - 1) {
            PHASE1_ST(((q + 1) & 1) * WBUF)
            STS_X(((q + 1) & 1) * XBUF)
        }
        __syncthreads();
    }

    // ---------- Phase 3: HMMA GEMM out[16][64] = wt @ W ----------
    {
        const int kh = wid >> 2;                 // K-half
        const int ng = wid & 3;                  // n-group (2 n-tiles)
        const int rowA = lane & 15;
        const uint32_t a_row = wt_u32 + rowA * ROWB;
        const int swA = rowA & 7;
        const int ks2b = kh * NKS + (lane >> 4); // 2*ks + khalf base

        float c0[4] = {0.f, 0.f, 0.f, 0.f};
        float c1[4] = {0.f, 0.f, 0.f, 0.f};
        const uint4* Bf = g_Bfrag4 + (ng * NKS + kh * (NKS / 2)) * 32 + lane;

        #pragma unroll 5
        for (int s = 0; s < NKS / 2; s++) {
            uint32_t addr = a_row + (((ks2b + 2 * s) ^ swA) << 4);
            uint32_t a0, a1, a2, a3;
            ldm_x4(a0, a1, a2, a3, addr);
            uint4 b = __ldg(Bf + s * 32);
            mma16816(c0, a0, a1, a2, a3, b.x, b.y);
            mma16816(c1, a0, a1, a2, a3, b.z, b.w);
        }

        // reduce across K-halves via smem (alias over x_sh region)
        float4* red4 = (float4*)(smem + XSH_OFF);    // 4KB <= 16KB
        __syncthreads();
        if (kh == 1) {
            red4[(ng * 2 + 0) * 32 + lane] = make_float4(c0[0], c0[1], c0[2], c0[3]);
            red4[(ng * 2 + 1) * 32 + lane] = make_float4(c1[0], c1[1], c1[2], c1[3]);
        }
        __syncthreads();
        if (kh == 0) {
            float4 r0 = red4[(ng * 2 + 0) * 32 + lane];
            float4 r1 = red4[(ng * 2 + 1) * 32 + lane];
            c0[0] += r0.x; c0[1] += r0.y; c0[2] += r0.z; c0[3] += r0.w;
            c1[0] += r1.x; c1[1] += r1.y; c1[2] += r1.z; c1[3] += r1.w;
            int ro0 = base + (lane >> 2);
            int ro1 = ro0 + 8;
            int col0 = (ng * 2 + 0) * 8 + (lane & 3) * 2;
            int col1 = (ng * 2 + 1) * 8 + (lane & 3) * 2;
            if (ro0 < N) {
                *(float2*)&out[(long long)ro0 * COUT + col0] = make_float2(c0[0], c0[1]);
                *(float2*)&out[(long long)ro0 * COUT + col1] = make_float2(c1[0], c1[1]);
            }
            if (ro1 < N) {
                *(float2*)&out[(long long)ro1 * COUT + col0] = make_float2(c0[2], c0[3]);
                *(float2*)&out[(long long)ro1 * COUT + col1] = make_float2(c1[2], c1[3]);
            }
        }
    }
}

extern "C" void kernel_launch(void* const* d_in, const int* in_sizes, int n_in,
                              void* d_out, int out_size) {
    const float* q_pts     = (const float*)d_in[0];
    const float* neighbors = (const float*)d_in[2];
    const float* x         = (const float*)d_in[4];
    const float* kp        = (const float*)d_in[5];
    const float* W         = (const float*)d_in[6];
    float* out = (float*)d_out;

    int N = in_sizes[0] / 3;

    cudaFuncSetAttribute(kpconv_kernel,
                         cudaFuncAttributeMaxDynamicSharedMemorySize, SMEM_TOTAL);

    pack_bfrag<<<(4 * NKS * 32 + 255) / 256, 256>>>(W);
    int grid = (N + PBLK - 1) / PBLK;
    kpconv_kernel<<<grid, THREADS, SMEM_TOTAL>>>(q_pts, neighbors, x, kp, out, N);
}